// round 16
// baseline (speedup 1.0000x reference)
#include <cuda_runtime.h>
#include <math.h>

// Problem max sizes (N=50000, E=800000)
#define NMAX 50000
#define EMAX 800000

// ---- static device scratch (zero-initialized at module load; the
// pipeline re-zeroes cnt/tile/tilectr/easum each run in k_scatter) ----
__device__ float  g_z[NMAX * 64];      // z of current layer (z0, then z1)
__device__ float  g_h[NMAX * 64];      // h of current layer
__device__ float  g_uv[NMAX * 64];     // [u | v] per node
__device__ __align__(16) float g_hdest[64];
__device__ double g_easum[2];
__device__ float  g_eamean[2];
// CSR by dst: packed edge payload {src, perm, ea.x(bits), ea.y(bits)}
__device__ int    g_cnt[NMAX];
__device__ int    g_rowptr[NMAX + 1];
__device__ int    g_rowcur[NMAX];
__device__ int4   g_epack[EMAX];
// decoupled-lookback scan state
__device__ unsigned long long g_tile[256];
__device__ int    g_tilectr;

// leaky relu, slope 0.2 < 1:  max(t, 0.2t) == leaky(t)
__device__ __forceinline__ float lrelu(float t) { return fmaxf(t, 0.2f * t); }

// ---- packed fp32x2 helpers (Blackwell FFMA2; used in k_gemv) ----
__device__ __forceinline__ unsigned long long pack2(float a, float b) {
    unsigned long long r;
    asm("mov.b64 %0, {%1, %2};" : "=l"(r) : "f"(a), "f"(b));
    return r;
}
__device__ __forceinline__ unsigned long long fma2(unsigned long long a,
                                                   unsigned long long b,
                                                   unsigned long long c) {
    unsigned long long d;
    asm("fma.rn.f32x2 %0, %1, %2, %3;" : "=l"(d) : "l"(a), "l"(b), "l"(c));
    return d;
}
__device__ __forceinline__ unsigned long long add2(unsigned long long a,
                                                   unsigned long long b) {
    unsigned long long d;
    asm("add.rn.f32x2 %0, %1, %2;" : "=l"(d) : "l"(a), "l"(b));
    return d;
}

// ============================================================
// 0) fused: edge_attr column sums + dst histogram (blocks [0,512))
//    + vectorized z0 = x@W0+b0 (blocks [512, 512+gN8))
// ============================================================
__global__ void k_easum_hist_z0(const int* __restrict__ ei,
                                const float2* __restrict__ ea,
                                const float2* __restrict__ x,
                                const float* __restrict__ W0,
                                const float* __restrict__ b0,
                                int N, int E) {
    if (blockIdx.x < 512) {
        double d0 = 0.0, d1 = 0.0;
        for (int i = blockIdx.x * 256 + threadIdx.x; i < E; i += 512 * 256) {
            float2 v = ea[i];
            d0 += (double)v.x; d1 += (double)v.y;
            atomicAdd(&g_cnt[ei[E + i]], 1);
        }
        __shared__ double sh0[256], sh1[256];
        int t = threadIdx.x;
        sh0[t] = d0; sh1[t] = d1;
        __syncthreads();
        for (int ofs = 128; ofs > 0; ofs >>= 1) {
            if (t < ofs) { sh0[t] += sh0[t + ofs]; sh1[t] += sh1[t + ofs]; }
            __syncthreads();
        }
        if (t == 0) {
            atomicAdd(&g_easum[0], sh0[0]);
            atomicAdd(&g_easum[1], sh1[0]);
        }
    } else {
        int i = (blockIdx.x - 512) * 256 + threadIdx.x;   // [0, N*8)
        if (i < N * 8) {
            int n = i >> 3, j = (i & 7) * 8;
            float2 xv = x[n];
            float4 w0a = *(const float4*)&W0[j];
            float4 w0b = *(const float4*)&W0[j + 4];
            float4 w1a = *(const float4*)&W0[64 + j];
            float4 w1b = *(const float4*)&W0[64 + j + 4];
            float4 ba  = *(const float4*)&b0[j];
            float4 bb  = *(const float4*)&b0[j + 4];
            float4 r0, r1;
            r0.x = fmaf(xv.x, w0a.x, fmaf(xv.y, w1a.x, ba.x));
            r0.y = fmaf(xv.x, w0a.y, fmaf(xv.y, w1a.y, ba.y));
            r0.z = fmaf(xv.x, w0a.z, fmaf(xv.y, w1a.z, ba.z));
            r0.w = fmaf(xv.x, w0a.w, fmaf(xv.y, w1a.w, ba.w));
            r1.x = fmaf(xv.x, w0b.x, fmaf(xv.y, w1b.x, bb.x));
            r1.y = fmaf(xv.x, w0b.y, fmaf(xv.y, w1b.y, bb.y));
            r1.z = fmaf(xv.x, w0b.z, fmaf(xv.y, w1b.z, bb.z));
            r1.w = fmaf(xv.x, w0b.w, fmaf(xv.y, w1b.w, bb.w));
            *(float4*)&g_z[n * 64 + j]     = r0;
            *(float4*)&g_z[n * 64 + j + 4] = r1;
        }
    }
}

// ============================================================
// 1) exclusive scan of g_cnt (decoupled lookback) + eamean
// ============================================================
__global__ void __launch_bounds__(256) k_scan(int N, int E) {
    __shared__ int sbid;
    __shared__ int swsum[8];
    __shared__ int sexcl;
    if (threadIdx.x == 0) sbid = atomicAdd(&g_tilectr, 1);
    __syncthreads();
    int bid = sbid;
    if (bid == 0 && threadIdx.x < 2)
        g_eamean[threadIdx.x] = (float)(g_easum[threadIdx.x] / (double)E);

    int i = bid * 256 + threadIdx.x;
    int v = (i < N) ? g_cnt[i] : 0;
    int lane = threadIdx.x & 31, w = threadIdx.x >> 5;
    int s = v;
#pragma unroll
    for (int o = 1; o < 32; o <<= 1) {
        int t = __shfl_up_sync(0xffffffffu, s, o);
        if (lane >= o) s += t;
    }
    if (lane == 31) swsum[w] = s;
    __syncthreads();
    if (w == 0) {
        int ws = (lane < 8) ? swsum[lane] : 0;
#pragma unroll
        for (int o = 1; o < 8; o <<= 1) {
            int t = __shfl_up_sync(0xffffffffu, ws, o);
            if (lane >= o) ws += t;
        }
        if (lane < 8) swsum[lane] = ws;
    }
    __syncthreads();
    int incl = s + (w > 0 ? swsum[w - 1] : 0);
    int btotal = swsum[7];

    if (threadIdx.x == 0) {
        unsigned long long word = (bid == 0)
            ? ((2ull << 32) | (unsigned)btotal)
            : ((1ull << 32) | (unsigned)btotal);
        atomicExch(&g_tile[bid], word);
    }

    if (bid > 0 && w == 0) {
        int excl = 0;
        int look = bid - 1 - lane;
        for (;;) {
            unsigned long long word = (look >= 0)
                ? atomicAdd(&g_tile[look], 0ull) : (2ull << 32);
            unsigned st = (unsigned)(word >> 32);
            unsigned pend = __ballot_sync(0xffffffffu, st == 0u);
            if (pend) continue;
            unsigned pre = __ballot_sync(0xffffffffu, st == 2u);
            int fp = __ffs(pre) - 1;
            int val = (int)(word & 0xffffffffu);
            if (fp >= 0) {
                int contrib = (lane <= fp && look >= 0) ? val : 0;
#pragma unroll
                for (int o = 16; o > 0; o >>= 1)
                    contrib += __shfl_xor_sync(0xffffffffu, contrib, o);
                excl += contrib;
                break;
            } else {
                int contrib = (look >= 0) ? val : 0;
#pragma unroll
                for (int o = 16; o > 0; o >>= 1)
                    contrib += __shfl_xor_sync(0xffffffffu, contrib, o);
                excl += contrib;
                look -= 32;
            }
        }
        if (lane == 0) {
            atomicExch(&g_tile[bid], (2ull << 32) | (unsigned)(excl + btotal));
            sexcl = excl;
        }
    } else if (threadIdx.x == 0) {
        sexcl = 0;
    }
    __syncthreads();
    int excl = sexcl;
    if (i < N) {
        int ip = excl + incl;
        g_rowptr[i + 1] = ip;
        g_rowcur[i] = ip - v;
    }
    if (i == 0) g_rowptr[0] = 0;
}

// ============================================================
// 2) packed CSR scatter (blocks [0,gE)) + re-zero state (rest)
// ============================================================
__global__ void k_scatter(const int* __restrict__ ei,
                          const float2* __restrict__ ea,
                          int N, int E, int gE) {
    if ((int)blockIdx.x < gE) {
        int e = blockIdx.x * 256 + threadIdx.x;
        if (e < E) {
            int dst = ei[E + e];
            int pos = atomicAdd(&g_rowcur[dst], 1);
            float2 a = ea[e];
            g_epack[pos] = make_int4(ei[e], e, __float_as_int(a.x),
                                     __float_as_int(a.y));
        }
    } else {
        int i = (blockIdx.x - gE) * 256 + threadIdx.x;
        if (i < N) g_cnt[i] = 0;
        if (i < 256) g_tile[i] = 0ull;
        if (i == 0) { g_tilectr = 0; g_easum[0] = 0.0; g_easum[1] = 0.0; }
    }
}

// ============================================================
// 3/5) GATv2 aggregation: fixed softmax reference + half-warp edge
// parallelism + 2-DEEP software pipeline (epack distance 2, z
// distance 1) so compute of quad k covers z-latency of quad k+1.
// ============================================================
__global__ void __launch_bounds__(128)
k_agg(const float* __restrict__ We, const float* __restrict__ att,
      const float* __restrict__ bias, const int* __restrict__ destp, int N) {
    int dst = (blockIdx.x * blockDim.x + threadIdx.x) >> 5;
    int lane = threadIdx.x & 31;
    if (dst >= N) return;
    int half = lane >> 4;
    int q = lane & 15;
    int ch = q * 4;

    float4 We0 = *(const float4*)&We[ch];
    float4 We1 = *(const float4*)&We[64 + ch];
    float4 at  = *(const float4*)&att[ch];
    float4 zd  = __ldg((const float4*)&g_z[dst * 64 + ch]);

    // self-loop logit = fixed softmax reference m
    float eax = g_eamean[0], eay = g_eamean[1];
    float t, m;
    t = lrelu(fmaf(eax, We0.x, fmaf(eay, We1.x, zd.x + zd.x))); m = t * at.x;
    t = lrelu(fmaf(eax, We0.y, fmaf(eay, We1.y, zd.y + zd.y))); m = fmaf(t, at.y, m);
    t = lrelu(fmaf(eax, We0.z, fmaf(eay, We1.z, zd.z + zd.z))); m = fmaf(t, at.z, m);
    t = lrelu(fmaf(eax, We0.w, fmaf(eay, We1.w, zd.w + zd.w))); m = fmaf(t, at.w, m);
#pragma unroll
    for (int o = 4; o >= 1; o >>= 1) m += __shfl_xor_sync(0xffffffffu, m, o);

    float denom = (half == 0) ? 1.f : 0.f;
    float4 acc;
    acc.x = (half == 0) ? zd.x : 0.f;
    acc.y = (half == 0) ? zd.y : 0.f;
    acc.z = (half == 0) ? zd.z : 0.f;
    acc.w = (half == 0) ? zd.w : 0.f;

    int idx = g_rowptr[dst], end = g_rowptr[dst + 1];

    // ---- 2-deep pipeline prologue ----
    int4 p0A, p0B, p1A, p1B;
    float4 z0A, z0B;
    if (idx + 4 <= end) {
        p0A = g_epack[idx + half];
        p0B = g_epack[idx + 2 + half];
        if (idx + 8 <= end) {
            p1A = g_epack[idx + 4 + half];
            p1B = g_epack[idx + 6 + half];
        }
        z0A = __ldg((const float4*)&g_z[p0A.x * 64 + ch]);
        z0B = __ldg((const float4*)&g_z[p0B.x * 64 + ch]);
    }
    while (idx + 4 <= end) {
        // issue next quad's z-gathers (p1 arrived during previous iteration)
        float4 z1A, z1B;
        if (idx + 8 <= end) {
            z1A = __ldg((const float4*)&g_z[p1A.x * 64 + ch]);
            z1B = __ldg((const float4*)&g_z[p1B.x * 64 + ch]);
        }
        // prefetch quad k+2's epack
        int4 p2A, p2B;
        if (idx + 12 <= end) {
            p2A = g_epack[idx + 8 + half];
            p2B = g_epack[idx + 10 + half];
        }

        float eAx = __int_as_float(p0A.z), eAy = __int_as_float(p0A.w);
        float eBx = __int_as_float(p0B.z), eBy = __int_as_float(p0B.w);
        float pa, pb;
        t = lrelu(fmaf(eAx, We0.x, fmaf(eAy, We1.x, zd.x + z0A.x))); pa = t * at.x;
        t = lrelu(fmaf(eAx, We0.y, fmaf(eAy, We1.y, zd.y + z0A.y))); pa = fmaf(t, at.y, pa);
        t = lrelu(fmaf(eAx, We0.z, fmaf(eAy, We1.z, zd.z + z0A.z))); pa = fmaf(t, at.z, pa);
        t = lrelu(fmaf(eAx, We0.w, fmaf(eAy, We1.w, zd.w + z0A.w))); pa = fmaf(t, at.w, pa);

        t = lrelu(fmaf(eBx, We0.x, fmaf(eBy, We1.x, zd.x + z0B.x))); pb = t * at.x;
        t = lrelu(fmaf(eBx, We0.y, fmaf(eBy, We1.y, zd.y + z0B.y))); pb = fmaf(t, at.y, pb);
        t = lrelu(fmaf(eBx, We0.z, fmaf(eBy, We1.z, zd.z + z0B.z))); pb = fmaf(t, at.z, pb);
        t = lrelu(fmaf(eBx, We0.w, fmaf(eBy, We1.w, zd.w + z0B.w))); pb = fmaf(t, at.w, pb);

#pragma unroll
        for (int o = 4; o >= 1; o >>= 1) {
            pa += __shfl_xor_sync(0xffffffffu, pa, o);
            pb += __shfl_xor_sync(0xffffffffu, pb, o);
        }
        float wa = __expf(pa - m);
        float wb = __expf(pb - m);
        denom += wa + wb;
        acc.x = fmaf(wa, z0A.x, acc.x); acc.x = fmaf(wb, z0B.x, acc.x);
        acc.y = fmaf(wa, z0A.y, acc.y); acc.y = fmaf(wb, z0B.y, acc.y);
        acc.z = fmaf(wa, z0A.z, acc.z); acc.z = fmaf(wb, z0B.z, acc.z);
        acc.w = fmaf(wa, z0A.w, acc.w); acc.w = fmaf(wb, z0B.w, acc.w);

        idx += 4;
        p0A = p1A; p0B = p1B;
        p1A = p2A; p1B = p2B;
        z0A = z1A; z0B = z1B;
    }
    // remainder: up to 3 edges, 2 at a time with validity guard
    for (; idx < end; idx += 2) {
        int e = idx + half;
        bool valid = e < end;
        int4 pR = g_epack[valid ? e : (end - 1)];
        float4 zA = __ldg((const float4*)&g_z[pR.x * 64 + ch]);
        float eAx = __int_as_float(pR.z), eAy = __int_as_float(pR.w);
        float pa;
        t = lrelu(fmaf(eAx, We0.x, fmaf(eAy, We1.x, zd.x + zA.x))); pa = t * at.x;
        t = lrelu(fmaf(eAx, We0.y, fmaf(eAy, We1.y, zd.y + zA.y))); pa = fmaf(t, at.y, pa);
        t = lrelu(fmaf(eAx, We0.z, fmaf(eAy, We1.z, zd.z + zA.z))); pa = fmaf(t, at.z, pa);
        t = lrelu(fmaf(eAx, We0.w, fmaf(eAy, We1.w, zd.w + zA.w))); pa = fmaf(t, at.w, pa);
#pragma unroll
        for (int o = 4; o >= 1; o >>= 1) pa += __shfl_xor_sync(0xffffffffu, pa, o);
        float wa = valid ? __expf(pa - m) : 0.f;
        denom += wa;
        acc.x = fmaf(wa, zA.x, acc.x);
        acc.y = fmaf(wa, zA.y, acc.y);
        acc.z = fmaf(wa, zA.z, acc.z);
        acc.w = fmaf(wa, zA.w, acc.w);
    }
    // merge half-warps (shared m -> plain addition)
    denom += __shfl_xor_sync(0xffffffffu, denom, 16);
    acc.x += __shfl_xor_sync(0xffffffffu, acc.x, 16);
    acc.y += __shfl_xor_sync(0xffffffffu, acc.y, 16);
    acc.z += __shfl_xor_sync(0xffffffffu, acc.z, 16);
    acc.w += __shfl_xor_sync(0xffffffffu, acc.w, 16);

    if (half == 0) {
        float inv = __fdividef(1.f, denom + 1e-16f);
        float4 b4 = *(const float4*)&bias[ch];
        float o; float4 h;
        o = fmaf(acc.x, inv, b4.x); h.x = (o > 0.f) ? o : expm1f(o);
        o = fmaf(acc.y, inv, b4.y); h.y = (o > 0.f) ? o : expm1f(o);
        o = fmaf(acc.z, inv, b4.z); h.z = (o > 0.f) ? o : expm1f(o);
        o = fmaf(acc.w, inv, b4.w); h.w = (o > 0.f) ? o : expm1f(o);
        *(float4*)&g_h[dst * 64 + ch] = h;
        if (destp && dst == destp[0]) *(float4*)&g_hdest[ch] = h;
    }
}

// ============================================================
// 4/6) register-tiled GEMM on device globals:
// mode 0: g_z[N,64]  = g_h[N,64] @ W (64x64 row-major) + bias
// mode 1: g_uv[N,64] = g_h[N,64] @ W' where
//         W'[k][j] = j<32 ? W[k*32+j] : W[(64+k)*32+j-32]   (no bias)
// ============================================================
__global__ void __launch_bounds__(128)
k_gemv(const float* __restrict__ W, const float* __restrict__ bias,
       int N, int mode) {
    __shared__ __align__(16) float sW[64 * 64];
    __shared__ __align__(16) float sA[64 * 68];

    for (int idx = threadIdx.x; idx < 4096; idx += 128) {
        int k = idx >> 6, j = idx & 63;
        sW[idx] = (mode == 0) ? W[idx]
                : ((j < 32) ? W[k * 32 + j] : W[(64 + k) * 32 + (j - 32)]);
    }
    int nbase = blockIdx.x * 64;
    for (int idx = threadIdx.x; idx < 64 * 16; idx += 128) {
        int n = idx >> 4, k4 = idx & 15;
        float4 av = (nbase + n < N)
            ? *(const float4*)&g_h[(nbase + n) * 64 + k4 * 4]
            : make_float4(0.f, 0.f, 0.f, 0.f);
        *(float4*)&sA[n * 68 + k4 * 4] = av;
    }
    __syncthreads();

    int cg = threadIdx.x & 7;        // channels cg*8 .. cg*8+7
    int ng = threadIdx.x >> 3;       // nodes ng*4 .. ng*4+3
    __align__(16) unsigned long long acc[4][4];
#pragma unroll
    for (int i = 0; i < 4; i++)
#pragma unroll
        for (int j = 0; j < 4; j++) acc[i][j] = 0ull;

    for (int k4 = 0; k4 < 16; k4++) {
        float4 a4[4];
#pragma unroll
        for (int i = 0; i < 4; i++)
            a4[i] = *(const float4*)&sA[(ng * 4 + i) * 68 + k4 * 4];
#pragma unroll
        for (int kk = 0; kk < 4; kk++) {
            int k = k4 * 4 + kk;
            ulonglong2 wl = *(const ulonglong2*)&sW[k * 64 + cg * 8];
            ulonglong2 wh = *(const ulonglong2*)&sW[k * 64 + cg * 8 + 4];
#pragma unroll
            for (int i = 0; i < 4; i++) {
                float a = (kk == 0) ? a4[i].x : (kk == 1) ? a4[i].y
                        : (kk == 2) ? a4[i].z : a4[i].w;
                unsigned long long aa = pack2(a, a);
                acc[i][0] = fma2(aa, wl.x, acc[i][0]);
                acc[i][1] = fma2(aa, wl.y, acc[i][1]);
                acc[i][2] = fma2(aa, wh.x, acc[i][2]);
                acc[i][3] = fma2(aa, wh.y, acc[i][3]);
            }
        }
    }
    if (mode == 0) {
        ulonglong2 b0 = *(const ulonglong2*)&bias[cg * 8];
        ulonglong2 b1v = *(const ulonglong2*)&bias[cg * 8 + 4];
#pragma unroll
        for (int i = 0; i < 4; i++) {
            acc[i][0] = add2(acc[i][0], b0.x);
            acc[i][1] = add2(acc[i][1], b0.y);
            acc[i][2] = add2(acc[i][2], b1v.x);
            acc[i][3] = add2(acc[i][3], b1v.y);
        }
    }
    float* C = (mode == 0) ? g_z : g_uv;
#pragma unroll
    for (int i = 0; i < 4; i++) {
        int n = nbase + ng * 4 + i;
        if (n < N) {
            *(float4*)&C[n * 64 + cg * 8]     = *(float4*)&acc[i][0];
            *(float4*)&C[n * 64 + cg * 8 + 4] = *(float4*)&acc[i][2];
        }
    }
}

// ============================================================
// 7) edge MLP, warp per dst node, 8 edges (2 quads) per iteration,
// dual prefetch — two independent u-gather wavefronts in flight.
// ============================================================
__global__ void __launch_bounds__(128)
k_edge(const float* __restrict__ Wm1, const float* __restrict__ bm1,
       const float* __restrict__ Wm2, const float* __restrict__ bm2,
       float* __restrict__ out, int N) {
    __shared__ float sg[32];
    if (threadIdx.x < 32) {
        int j = threadIdx.x;
        float acc = bm1[j];
#pragma unroll
        for (int k = 0; k < 64; k++)
            acc = fmaf(g_hdest[k], Wm1[(128 + k) * 32 + j], acc);
        sg[j] = acc;
    }
    __syncthreads();

    int warp = (blockIdx.x * blockDim.x + threadIdx.x) >> 5;
    int lane = threadIdx.x & 31;
    if (warp >= N) return;
    int dst = warp;
    int g = lane >> 3;          // edge slot 0..3 within a quad
    int l = lane & 7;           // channel block: channels [4l, 4l+4)

    float4 v4 = __ldg((const float4*)&g_uv[dst * 64 + 32 + l * 4]);
    float4 gv = *(const float4*)&sg[l * 4];
    float4 w0 = __ldg(&((const float4*)&Wm1[192 * 32])[l]);
    float4 w1 = __ldg(&((const float4*)&Wm1[193 * 32])[l]);
    float4 w2 = __ldg(&((const float4*)Wm2)[l]);
    float bm2v = bm2[0];
    float bx = v4.x + gv.x, by = v4.y + gv.y;
    float bz = v4.z + gv.z, bw = v4.w + gv.w;

    int start = g_rowptr[dst], end = g_rowptr[dst + 1];
    if (start >= end) return;
    int last = end - 1;
    int e1 = start + g;
    int e2 = start + 4 + g;
    int4 pk1 = g_epack[(e1 < end) ? e1 : last];
    int4 pk2 = g_epack[(e2 < end) ? e2 : last];
    for (int idx = start; idx < end; idx += 8) {
        bool v1 = (idx + g) < end;
        bool v2 = (idx + 4 + g) < end;
        float4 u1 = __ldg((const float4*)&g_uv[pk1.x * 64 + l * 4]);
        float4 u2 = __ldg((const float4*)&g_uv[pk2.x * 64 + l * 4]);
        float a1x = __int_as_float(pk1.z), a1y = __int_as_float(pk1.w);
        float a2x = __int_as_float(pk2.z), a2y = __int_as_float(pk2.w);
        int perm1 = pk1.y, perm2 = pk2.y;
        if (idx + 8 < end) {
            int n1 = idx + 8 + g;
            int n2 = idx + 12 + g;
            pk1 = g_epack[(n1 < end) ? n1 : last];
            pk2 = g_epack[(n2 < end) ? n2 : last];
        }

        float m0 = fmaf(a1x, w0.x, fmaf(a1y, w1.x, u1.x + bx));
        float m1 = fmaf(a1x, w0.y, fmaf(a1y, w1.y, u1.y + by));
        float m2 = fmaf(a1x, w0.z, fmaf(a1y, w1.z, u1.z + bz));
        float m3 = fmaf(a1x, w0.w, fmaf(a1y, w1.w, u1.w + bw));
        float n0 = fmaf(a2x, w0.x, fmaf(a2y, w1.x, u2.x + bx));
        float n1_ = fmaf(a2x, w0.y, fmaf(a2y, w1.y, u2.y + by));
        float n2_ = fmaf(a2x, w0.z, fmaf(a2y, w1.z, u2.z + bz));
        float n3_ = fmaf(a2x, w0.w, fmaf(a2y, w1.w, u2.w + bw));
        m0 = fmaxf(m0, 0.f); m1 = fmaxf(m1, 0.f);
        m2 = fmaxf(m2, 0.f); m3 = fmaxf(m3, 0.f);
        n0 = fmaxf(n0, 0.f); n1_ = fmaxf(n1_, 0.f);
        n2_ = fmaxf(n2_, 0.f); n3_ = fmaxf(n3_, 0.f);
        float s1 = fmaf(m0, w2.x, fmaf(m1, w2.y, fmaf(m2, w2.z, m3 * w2.w)));
        float s2 = fmaf(n0, w2.x, fmaf(n1_, w2.y, fmaf(n2_, w2.z, n3_ * w2.w)));
#pragma unroll
        for (int o = 4; o >= 1; o >>= 1) {
            s1 += __shfl_xor_sync(0xffffffffu, s1, o);
            s2 += __shfl_xor_sync(0xffffffffu, s2, o);
        }
        if (l == 0) {
            if (v1) out[perm1] = s1 + bm2v;
            if (v2) out[perm2] = s2 + bm2v;
        }
    }
}

// ============================================================
extern "C" void kernel_launch(void* const* d_in, const int* in_sizes, int n_in,
                              void* d_out, int out_size) {
    const float* x     = (const float*)d_in[0];
    const int*   ei    = (const int*)d_in[1];
    const float* ea    = (const float*)d_in[2];
    const int*   dest  = (const int*)d_in[3];
    const float* W0    = (const float*)d_in[4];
    const float* b0    = (const float*)d_in[5];
    const float* We0   = (const float*)d_in[6];
    const float* att0  = (const float*)d_in[7];
    const float* bias0 = (const float*)d_in[8];
    const float* W1    = (const float*)d_in[9];
    const float* b1    = (const float*)d_in[10];
    const float* We1   = (const float*)d_in[11];
    const float* att1  = (const float*)d_in[12];
    const float* bias1 = (const float*)d_in[13];
    const float* Wm1   = (const float*)d_in[14];
    const float* bm1   = (const float*)d_in[15];
    const float* Wm2   = (const float*)d_in[16];
    const float* bm2   = (const float*)d_in[17];

    int N = in_sizes[0] / 2;
    int E = in_sizes[1] / 2;

    const int TB = 256;
    int gE    = (E + TB - 1) / TB;
    int gN    = (N + TB - 1) / TB;
    int gN8   = (N * 8 + TB - 1) / TB;
    int gAgg  = (N * 32 + 127) / 128;   // 128-thread blocks, warp per dst
    int gGemv = (N + 63) / 64;
    int nSB   = (N + 255) / 256;

    k_easum_hist_z0<<<512 + gN8, TB>>>(ei, (const float2*)ea,
                                       (const float2*)x, W0, b0, N, E);  // 0
    k_scan<<<nSB, 256>>>(N, E);                                          // 1
    k_scatter<<<gE + gN, TB>>>(ei, (const float2*)ea, N, E, gE);         // 2
    // layer 0
    k_agg<<<gAgg, 128>>>(We0, att0, bias0, (const int*)0, N);            // 3 (profiled)
    k_gemv<<<gGemv, 128>>>(W1, b1, N, 0);                                // 4
    // layer 1
    k_agg<<<gAgg, 128>>>(We1, att1, bias1, dest, N);                     // 5
    k_gemv<<<gGemv, 128>>>(Wm1, (const float*)0, N, 1);                  // 6
    // edge scoring head
    k_edge<<<gAgg, 128>>>(Wm1, bm1, Wm2, bm2, (float*)d_out, N);         // 7
}

// round 17
// speedup vs baseline: 1.0990x; 1.0990x over previous
#include <cuda_runtime.h>
#include <math.h>

// Problem max sizes (N=50000, E=800000)
#define NMAX 50000
#define EMAX 800000

// ---- static device scratch (zero-initialized at module load; the
// pipeline re-zeroes cnt/tile/tilectr/easum each run in k_scatter) ----
__device__ float  g_z[NMAX * 64];      // z of current layer (z0, then z1)
__device__ float  g_h[NMAX * 64];      // h of current layer
__device__ float  g_uv[NMAX * 64];     // [u | v] per node
__device__ __align__(16) float g_hdest[64];
__device__ __align__(16) float g_gvec[32];   // h[dest]@Wm1[128:192] + bm1
__device__ double g_easum[2];
__device__ float  g_eamean[2];
// CSR by dst: packed edge payload {src, perm, ea.x(bits), ea.y(bits)}
__device__ int    g_cnt[NMAX];
__device__ int    g_rowptr[NMAX + 1];
__device__ int    g_rowcur[NMAX];
__device__ int4   g_epack[EMAX];
// decoupled-lookback scan state
__device__ unsigned long long g_tile[256];
__device__ int    g_tilectr;

// leaky relu, slope 0.2 < 1:  max(t, 0.2t) == leaky(t)
__device__ __forceinline__ float lrelu(float t) { return fmaxf(t, 0.2f * t); }

// ---- packed fp32x2 helpers (Blackwell FFMA2; used in k_gemv) ----
__device__ __forceinline__ unsigned long long pack2(float a, float b) {
    unsigned long long r;
    asm("mov.b64 %0, {%1, %2};" : "=l"(r) : "f"(a), "f"(b));
    return r;
}
__device__ __forceinline__ unsigned long long fma2(unsigned long long a,
                                                   unsigned long long b,
                                                   unsigned long long c) {
    unsigned long long d;
    asm("fma.rn.f32x2 %0, %1, %2, %3;" : "=l"(d) : "l"(a), "l"(b), "l"(c));
    return d;
}
__device__ __forceinline__ unsigned long long add2(unsigned long long a,
                                                   unsigned long long b) {
    unsigned long long d;
    asm("add.rn.f32x2 %0, %1, %2;" : "=l"(d) : "l"(a), "l"(b));
    return d;
}

// ============================================================
// 0) fused: edge_attr column sums + dst histogram (blocks [0,512))
//    + vectorized z0 = x@W0+b0 (blocks [512, 512+gN8))
// ============================================================
__global__ void k_easum_hist_z0(const int* __restrict__ ei,
                                const float2* __restrict__ ea,
                                const float2* __restrict__ x,
                                const float* __restrict__ W0,
                                const float* __restrict__ b0,
                                int N, int E) {
    if (blockIdx.x < 512) {
        double d0 = 0.0, d1 = 0.0;
        for (int i = blockIdx.x * 256 + threadIdx.x; i < E; i += 512 * 256) {
            float2 v = ea[i];
            d0 += (double)v.x; d1 += (double)v.y;
            atomicAdd(&g_cnt[ei[E + i]], 1);
        }
        __shared__ double sh0[256], sh1[256];
        int t = threadIdx.x;
        sh0[t] = d0; sh1[t] = d1;
        __syncthreads();
        for (int ofs = 128; ofs > 0; ofs >>= 1) {
            if (t < ofs) { sh0[t] += sh0[t + ofs]; sh1[t] += sh1[t + ofs]; }
            __syncthreads();
        }
        if (t == 0) {
            atomicAdd(&g_easum[0], sh0[0]);
            atomicAdd(&g_easum[1], sh1[0]);
        }
    } else {
        int i = (blockIdx.x - 512) * 256 + threadIdx.x;   // [0, N*8)
        if (i < N * 8) {
            int n = i >> 3, j = (i & 7) * 8;
            float2 xv = x[n];
            float4 w0a = *(const float4*)&W0[j];
            float4 w0b = *(const float4*)&W0[j + 4];
            float4 w1a = *(const float4*)&W0[64 + j];
            float4 w1b = *(const float4*)&W0[64 + j + 4];
            float4 ba  = *(const float4*)&b0[j];
            float4 bb  = *(const float4*)&b0[j + 4];
            float4 r0, r1;
            r0.x = fmaf(xv.x, w0a.x, fmaf(xv.y, w1a.x, ba.x));
            r0.y = fmaf(xv.x, w0a.y, fmaf(xv.y, w1a.y, ba.y));
            r0.z = fmaf(xv.x, w0a.z, fmaf(xv.y, w1a.z, ba.z));
            r0.w = fmaf(xv.x, w0a.w, fmaf(xv.y, w1a.w, ba.w));
            r1.x = fmaf(xv.x, w0b.x, fmaf(xv.y, w1b.x, bb.x));
            r1.y = fmaf(xv.x, w0b.y, fmaf(xv.y, w1b.y, bb.y));
            r1.z = fmaf(xv.x, w0b.z, fmaf(xv.y, w1b.z, bb.z));
            r1.w = fmaf(xv.x, w0b.w, fmaf(xv.y, w1b.w, bb.w));
            *(float4*)&g_z[n * 64 + j]     = r0;
            *(float4*)&g_z[n * 64 + j + 4] = r1;
        }
    }
}

// ============================================================
// 1) exclusive scan of g_cnt (decoupled lookback) + eamean
// ============================================================
__global__ void __launch_bounds__(256) k_scan(int N, int E) {
    __shared__ int sbid;
    __shared__ int swsum[8];
    __shared__ int sexcl;
    if (threadIdx.x == 0) sbid = atomicAdd(&g_tilectr, 1);
    __syncthreads();
    int bid = sbid;
    if (bid == 0 && threadIdx.x < 2)
        g_eamean[threadIdx.x] = (float)(g_easum[threadIdx.x] / (double)E);

    int i = bid * 256 + threadIdx.x;
    int v = (i < N) ? g_cnt[i] : 0;
    int lane = threadIdx.x & 31, w = threadIdx.x >> 5;
    int s = v;
#pragma unroll
    for (int o = 1; o < 32; o <<= 1) {
        int t = __shfl_up_sync(0xffffffffu, s, o);
        if (lane >= o) s += t;
    }
    if (lane == 31) swsum[w] = s;
    __syncthreads();
    if (w == 0) {
        int ws = (lane < 8) ? swsum[lane] : 0;
#pragma unroll
        for (int o = 1; o < 8; o <<= 1) {
            int t = __shfl_up_sync(0xffffffffu, ws, o);
            if (lane >= o) ws += t;
        }
        if (lane < 8) swsum[lane] = ws;
    }
    __syncthreads();
    int incl = s + (w > 0 ? swsum[w - 1] : 0);
    int btotal = swsum[7];

    if (threadIdx.x == 0) {
        unsigned long long word = (bid == 0)
            ? ((2ull << 32) | (unsigned)btotal)
            : ((1ull << 32) | (unsigned)btotal);
        atomicExch(&g_tile[bid], word);
    }

    if (bid > 0 && w == 0) {
        int excl = 0;
        int look = bid - 1 - lane;
        for (;;) {
            unsigned long long word = (look >= 0)
                ? atomicAdd(&g_tile[look], 0ull) : (2ull << 32);
            unsigned st = (unsigned)(word >> 32);
            unsigned pend = __ballot_sync(0xffffffffu, st == 0u);
            if (pend) continue;
            unsigned pre = __ballot_sync(0xffffffffu, st == 2u);
            int fp = __ffs(pre) - 1;
            int val = (int)(word & 0xffffffffu);
            if (fp >= 0) {
                int contrib = (lane <= fp && look >= 0) ? val : 0;
#pragma unroll
                for (int o = 16; o > 0; o >>= 1)
                    contrib += __shfl_xor_sync(0xffffffffu, contrib, o);
                excl += contrib;
                break;
            } else {
                int contrib = (look >= 0) ? val : 0;
#pragma unroll
                for (int o = 16; o > 0; o >>= 1)
                    contrib += __shfl_xor_sync(0xffffffffu, contrib, o);
                excl += contrib;
                look -= 32;
            }
        }
        if (lane == 0) {
            atomicExch(&g_tile[bid], (2ull << 32) | (unsigned)(excl + btotal));
            sexcl = excl;
        }
    } else if (threadIdx.x == 0) {
        sexcl = 0;
    }
    __syncthreads();
    int excl = sexcl;
    if (i < N) {
        int ip = excl + incl;
        g_rowptr[i + 1] = ip;
        g_rowcur[i] = ip - v;
    }
    if (i == 0) g_rowptr[0] = 0;
}

// ============================================================
// 2) packed CSR scatter (blocks [0,gE)) + re-zero state (rest)
// ============================================================
__global__ void k_scatter(const int* __restrict__ ei,
                          const float2* __restrict__ ea,
                          int N, int E, int gE) {
    if ((int)blockIdx.x < gE) {
        int e = blockIdx.x * 256 + threadIdx.x;
        if (e < E) {
            int dst = ei[E + e];
            int pos = atomicAdd(&g_rowcur[dst], 1);
            float2 a = ea[e];
            g_epack[pos] = make_int4(ei[e], e, __float_as_int(a.x),
                                     __float_as_int(a.y));
        }
    } else {
        int i = (blockIdx.x - gE) * 256 + threadIdx.x;
        if (i < N) g_cnt[i] = 0;
        if (i < 256) g_tile[i] = 0ull;
        if (i == 0) { g_tilectr = 0; g_easum[0] = 0.0; g_easum[1] = 0.0; }
    }
}

// ============================================================
// 3/5) GATv2 aggregation (R15 form — best measured): fixed softmax
// reference + half-warp edge parallelism + 1-deep epack prefetch +
// nested-FMA logits + FMNMX leaky. 128-thread blocks.
// ============================================================
__global__ void __launch_bounds__(128)
k_agg(const float* __restrict__ We, const float* __restrict__ att,
      const float* __restrict__ bias, const int* __restrict__ destp, int N) {
    int dst = (blockIdx.x * blockDim.x + threadIdx.x) >> 5;
    int lane = threadIdx.x & 31;
    if (dst >= N) return;
    int half = lane >> 4;
    int q = lane & 15;
    int ch = q * 4;

    float4 We0 = *(const float4*)&We[ch];
    float4 We1 = *(const float4*)&We[64 + ch];
    float4 at  = *(const float4*)&att[ch];
    float4 zd  = __ldg((const float4*)&g_z[dst * 64 + ch]);

    // self-loop logit = fixed softmax reference m
    float eax = g_eamean[0], eay = g_eamean[1];
    float t, m;
    t = lrelu(fmaf(eax, We0.x, fmaf(eay, We1.x, zd.x + zd.x))); m = t * at.x;
    t = lrelu(fmaf(eax, We0.y, fmaf(eay, We1.y, zd.y + zd.y))); m = fmaf(t, at.y, m);
    t = lrelu(fmaf(eax, We0.z, fmaf(eay, We1.z, zd.z + zd.z))); m = fmaf(t, at.z, m);
    t = lrelu(fmaf(eax, We0.w, fmaf(eay, We1.w, zd.w + zd.w))); m = fmaf(t, at.w, m);
#pragma unroll
    for (int o = 4; o >= 1; o >>= 1) m += __shfl_xor_sync(0xffffffffu, m, o);

    float denom = (half == 0) ? 1.f : 0.f;
    float4 acc;
    acc.x = (half == 0) ? zd.x : 0.f;
    acc.y = (half == 0) ? zd.y : 0.f;
    acc.z = (half == 0) ? zd.z : 0.f;
    acc.w = (half == 0) ? zd.w : 0.f;

    int idx = g_rowptr[dst], end = g_rowptr[dst + 1];

    // prologue: prefetch first epack quad
    int4 pA, pB;
    if (idx + 4 <= end) {
        pA = g_epack[idx + half];
        pB = g_epack[idx + 2 + half];
    }
    while (idx + 4 <= end) {
        float4 zA = __ldg((const float4*)&g_z[pA.x * 64 + ch]);
        float4 zB = __ldg((const float4*)&g_z[pB.x * 64 + ch]);
        float eAx = __int_as_float(pA.z), eAy = __int_as_float(pA.w);
        float eBx = __int_as_float(pB.z), eBy = __int_as_float(pB.w);
        idx += 4;
        int4 nA, nB;
        if (idx + 4 <= end) {
            nA = g_epack[idx + half];
            nB = g_epack[idx + 2 + half];
        }

        float pa, pb;
        t = lrelu(fmaf(eAx, We0.x, fmaf(eAy, We1.x, zd.x + zA.x))); pa = t * at.x;
        t = lrelu(fmaf(eAx, We0.y, fmaf(eAy, We1.y, zd.y + zA.y))); pa = fmaf(t, at.y, pa);
        t = lrelu(fmaf(eAx, We0.z, fmaf(eAy, We1.z, zd.z + zA.z))); pa = fmaf(t, at.z, pa);
        t = lrelu(fmaf(eAx, We0.w, fmaf(eAy, We1.w, zd.w + zA.w))); pa = fmaf(t, at.w, pa);

        t = lrelu(fmaf(eBx, We0.x, fmaf(eBy, We1.x, zd.x + zB.x))); pb = t * at.x;
        t = lrelu(fmaf(eBx, We0.y, fmaf(eBy, We1.y, zd.y + zB.y))); pb = fmaf(t, at.y, pb);
        t = lrelu(fmaf(eBx, We0.z, fmaf(eBy, We1.z, zd.z + zB.z))); pb = fmaf(t, at.z, pb);
        t = lrelu(fmaf(eBx, We0.w, fmaf(eBy, We1.w, zd.w + zB.w))); pb = fmaf(t, at.w, pb);

#pragma unroll
        for (int o = 4; o >= 1; o >>= 1) {
            pa += __shfl_xor_sync(0xffffffffu, pa, o);
            pb += __shfl_xor_sync(0xffffffffu, pb, o);
        }
        float wa = __expf(pa - m);
        float wb = __expf(pb - m);
        denom += wa + wb;
        acc.x = fmaf(wa, zA.x, acc.x); acc.x = fmaf(wb, zB.x, acc.x);
        acc.y = fmaf(wa, zA.y, acc.y); acc.y = fmaf(wb, zB.y, acc.y);
        acc.z = fmaf(wa, zA.z, acc.z); acc.z = fmaf(wb, zB.z, acc.z);
        acc.w = fmaf(wa, zA.w, acc.w); acc.w = fmaf(wb, zB.w, acc.w);
        pA = nA; pB = nB;
    }
    // remainder: up to 3 edges, 2 at a time with validity guard
    for (; idx < end; idx += 2) {
        int e = idx + half;
        bool valid = e < end;
        int4 pR = g_epack[valid ? e : (end - 1)];
        float4 zA = __ldg((const float4*)&g_z[pR.x * 64 + ch]);
        float eAx = __int_as_float(pR.z), eAy = __int_as_float(pR.w);
        float pa;
        t = lrelu(fmaf(eAx, We0.x, fmaf(eAy, We1.x, zd.x + zA.x))); pa = t * at.x;
        t = lrelu(fmaf(eAx, We0.y, fmaf(eAy, We1.y, zd.y + zA.y))); pa = fmaf(t, at.y, pa);
        t = lrelu(fmaf(eAx, We0.z, fmaf(eAy, We1.z, zd.z + zA.z))); pa = fmaf(t, at.z, pa);
        t = lrelu(fmaf(eAx, We0.w, fmaf(eAy, We1.w, zd.w + zA.w))); pa = fmaf(t, at.w, pa);
#pragma unroll
        for (int o = 4; o >= 1; o >>= 1) pa += __shfl_xor_sync(0xffffffffu, pa, o);
        float wa = valid ? __expf(pa - m) : 0.f;
        denom += wa;
        acc.x = fmaf(wa, zA.x, acc.x);
        acc.y = fmaf(wa, zA.y, acc.y);
        acc.z = fmaf(wa, zA.z, acc.z);
        acc.w = fmaf(wa, zA.w, acc.w);
    }
    // merge half-warps (shared m -> plain addition)
    denom += __shfl_xor_sync(0xffffffffu, denom, 16);
    acc.x += __shfl_xor_sync(0xffffffffu, acc.x, 16);
    acc.y += __shfl_xor_sync(0xffffffffu, acc.y, 16);
    acc.z += __shfl_xor_sync(0xffffffffu, acc.z, 16);
    acc.w += __shfl_xor_sync(0xffffffffu, acc.w, 16);

    if (half == 0) {
        float inv = __fdividef(1.f, denom + 1e-16f);
        float4 b4 = *(const float4*)&bias[ch];
        float o; float4 h;
        o = fmaf(acc.x, inv, b4.x); h.x = (o > 0.f) ? o : expm1f(o);
        o = fmaf(acc.y, inv, b4.y); h.y = (o > 0.f) ? o : expm1f(o);
        o = fmaf(acc.z, inv, b4.z); h.z = (o > 0.f) ? o : expm1f(o);
        o = fmaf(acc.w, inv, b4.w); h.w = (o > 0.f) ? o : expm1f(o);
        *(float4*)&g_h[dst * 64 + ch] = h;
        if (destp && dst == destp[0]) *(float4*)&g_hdest[ch] = h;
    }
}

// ============================================================
// 4/6) register-tiled GEMM on device globals:
// mode 0: g_z[N,64]  = g_h[N,64] @ W (64x64 row-major) + bias
// mode 1: g_uv[N,64] = g_h[N,64] @ W' (re-indexed Wm1[0:128]);
//         block 0 additionally computes g_gvec from g_hdest.
// ============================================================
__global__ void __launch_bounds__(128)
k_gemv(const float* __restrict__ W, const float* __restrict__ bias,
       int N, int mode) {
    __shared__ __align__(16) float sW[64 * 64];
    __shared__ __align__(16) float sA[64 * 68];

    for (int idx = threadIdx.x; idx < 4096; idx += 128) {
        int k = idx >> 6, j = idx & 63;
        sW[idx] = (mode == 0) ? W[idx]
                : ((j < 32) ? W[k * 32 + j] : W[(64 + k) * 32 + (j - 32)]);
    }
    int nbase = blockIdx.x * 64;
    for (int idx = threadIdx.x; idx < 64 * 16; idx += 128) {
        int n = idx >> 4, k4 = idx & 15;
        float4 av = (nbase + n < N)
            ? *(const float4*)&g_h[(nbase + n) * 64 + k4 * 4]
            : make_float4(0.f, 0.f, 0.f, 0.f);
        *(float4*)&sA[n * 68 + k4 * 4] = av;
    }
    // mode 1, block 0: compute g_gvec = h[dest]@Wm1[128:192] + bm1
    // (bias ptr carries bm1 in mode 1; g_hdest ready after k_agg1)
    if (mode == 1 && blockIdx.x == 0 && threadIdx.x < 32) {
        int j = threadIdx.x;
        float acc = bias[j];
#pragma unroll
        for (int k = 0; k < 64; k++)
            acc = fmaf(g_hdest[k], W[(128 + k) * 32 + j], acc);
        g_gvec[j] = acc;
    }
    __syncthreads();

    int cg = threadIdx.x & 7;        // channels cg*8 .. cg*8+7
    int ng = threadIdx.x >> 3;       // nodes ng*4 .. ng*4+3
    __align__(16) unsigned long long acc[4][4];
#pragma unroll
    for (int i = 0; i < 4; i++)
#pragma unroll
        for (int j = 0; j < 4; j++) acc[i][j] = 0ull;

    for (int k4 = 0; k4 < 16; k4++) {
        float4 a4[4];
#pragma unroll
        for (int i = 0; i < 4; i++)
            a4[i] = *(const float4*)&sA[(ng * 4 + i) * 68 + k4 * 4];
#pragma unroll
        for (int kk = 0; kk < 4; kk++) {
            int k = k4 * 4 + kk;
            ulonglong2 wl = *(const ulonglong2*)&sW[k * 64 + cg * 8];
            ulonglong2 wh = *(const ulonglong2*)&sW[k * 64 + cg * 8 + 4];
#pragma unroll
            for (int i = 0; i < 4; i++) {
                float a = (kk == 0) ? a4[i].x : (kk == 1) ? a4[i].y
                        : (kk == 2) ? a4[i].z : a4[i].w;
                unsigned long long aa = pack2(a, a);
                acc[i][0] = fma2(aa, wl.x, acc[i][0]);
                acc[i][1] = fma2(aa, wl.y, acc[i][1]);
                acc[i][2] = fma2(aa, wh.x, acc[i][2]);
                acc[i][3] = fma2(aa, wh.y, acc[i][3]);
            }
        }
    }
    if (mode == 0) {
        ulonglong2 b0 = *(const ulonglong2*)&bias[cg * 8];
        ulonglong2 b1v = *(const ulonglong2*)&bias[cg * 8 + 4];
#pragma unroll
        for (int i = 0; i < 4; i++) {
            acc[i][0] = add2(acc[i][0], b0.x);
            acc[i][1] = add2(acc[i][1], b0.y);
            acc[i][2] = add2(acc[i][2], b1v.x);
            acc[i][3] = add2(acc[i][3], b1v.y);
        }
    }
    float* C = (mode == 0) ? g_z : g_uv;
#pragma unroll
    for (int i = 0; i < 4; i++) {
        int n = nbase + ng * 4 + i;
        if (n < N) {
            *(float4*)&C[n * 64 + cg * 8]     = *(float4*)&acc[i][0];
            *(float4*)&C[n * 64 + cg * 8 + 4] = *(float4*)&acc[i][2];
        }
    }
}

// ============================================================
// 7) edge MLP, warp per dst node, 8 edges (2 quads) per iteration,
// dual prefetch. gvec precomputed (no per-block prologue/sync).
// ============================================================
__global__ void __launch_bounds__(128)
k_edge(const float* __restrict__ Wm1, const float* __restrict__ Wm2,
       const float* __restrict__ bm2, float* __restrict__ out, int N) {
    int warp = (blockIdx.x * blockDim.x + threadIdx.x) >> 5;
    int lane = threadIdx.x & 31;
    if (warp >= N) return;
    int dst = warp;
    int g = lane >> 3;          // edge slot 0..3 within a quad
    int l = lane & 7;           // channel block: channels [4l, 4l+4)

    float4 v4 = __ldg((const float4*)&g_uv[dst * 64 + 32 + l * 4]);
    float4 gv = *(const float4*)&g_gvec[l * 4];
    float4 w0 = __ldg(&((const float4*)&Wm1[192 * 32])[l]);
    float4 w1 = __ldg(&((const float4*)&Wm1[193 * 32])[l]);
    float4 w2 = __ldg(&((const float4*)Wm2)[l]);
    float bm2v = bm2[0];
    float bx = v4.x + gv.x, by = v4.y + gv.y;
    float bz = v4.z + gv.z, bw = v4.w + gv.w;

    int start = g_rowptr[dst], end = g_rowptr[dst + 1];
    if (start >= end) return;
    int last = end - 1;
    int e1 = start + g;
    int e2 = start + 4 + g;
    int4 pk1 = g_epack[(e1 < end) ? e1 : last];
    int4 pk2 = g_epack[(e2 < end) ? e2 : last];
    for (int idx = start; idx < end; idx += 8) {
        bool v1 = (idx + g) < end;
        bool v2 = (idx + 4 + g) < end;
        float4 u1 = __ldg((const float4*)&g_uv[pk1.x * 64 + l * 4]);
        float4 u2 = __ldg((const float4*)&g_uv[pk2.x * 64 + l * 4]);
        float a1x = __int_as_float(pk1.z), a1y = __int_as_float(pk1.w);
        float a2x = __int_as_float(pk2.z), a2y = __int_as_float(pk2.w);
        int perm1 = pk1.y, perm2 = pk2.y;
        if (idx + 8 < end) {
            int n1 = idx + 8 + g;
            int n2 = idx + 12 + g;
            pk1 = g_epack[(n1 < end) ? n1 : last];
            pk2 = g_epack[(n2 < end) ? n2 : last];
        }

        float m0 = fmaf(a1x, w0.x, fmaf(a1y, w1.x, u1.x + bx));
        float m1 = fmaf(a1x, w0.y, fmaf(a1y, w1.y, u1.y + by));
        float m2 = fmaf(a1x, w0.z, fmaf(a1y, w1.z, u1.z + bz));
        float m3 = fmaf(a1x, w0.w, fmaf(a1y, w1.w, u1.w + bw));
        float n0 = fmaf(a2x, w0.x, fmaf(a2y, w1.x, u2.x + bx));
        float n1_ = fmaf(a2x, w0.y, fmaf(a2y, w1.y, u2.y + by));
        float n2_ = fmaf(a2x, w0.z, fmaf(a2y, w1.z, u2.z + bz));
        float n3_ = fmaf(a2x, w0.w, fmaf(a2y, w1.w, u2.w + bw));
        m0 = fmaxf(m0, 0.f); m1 = fmaxf(m1, 0.f);
        m2 = fmaxf(m2, 0.f); m3 = fmaxf(m3, 0.f);
        n0 = fmaxf(n0, 0.f); n1_ = fmaxf(n1_, 0.f);
        n2_ = fmaxf(n2_, 0.f); n3_ = fmaxf(n3_, 0.f);
        float s1 = fmaf(m0, w2.x, fmaf(m1, w2.y, fmaf(m2, w2.z, m3 * w2.w)));
        float s2 = fmaf(n0, w2.x, fmaf(n1_, w2.y, fmaf(n2_, w2.z, n3_ * w2.w)));
#pragma unroll
        for (int o = 4; o >= 1; o >>= 1) {
            s1 += __shfl_xor_sync(0xffffffffu, s1, o);
            s2 += __shfl_xor_sync(0xffffffffu, s2, o);
        }
        if (l == 0) {
            if (v1) out[perm1] = s1 + bm2v;
            if (v2) out[perm2] = s2 + bm2v;
        }
    }
}

// ============================================================
extern "C" void kernel_launch(void* const* d_in, const int* in_sizes, int n_in,
                              void* d_out, int out_size) {
    const float* x     = (const float*)d_in[0];
    const int*   ei    = (const int*)d_in[1];
    const float* ea    = (const float*)d_in[2];
    const int*   dest  = (const int*)d_in[3];
    const float* W0    = (const float*)d_in[4];
    const float* b0    = (const float*)d_in[5];
    const float* We0   = (const float*)d_in[6];
    const float* att0  = (const float*)d_in[7];
    const float* bias0 = (const float*)d_in[8];
    const float* W1    = (const float*)d_in[9];
    const float* b1    = (const float*)d_in[10];
    const float* We1   = (const float*)d_in[11];
    const float* att1  = (const float*)d_in[12];
    const float* bias1 = (const float*)d_in[13];
    const float* Wm1   = (const float*)d_in[14];
    const float* bm1   = (const float*)d_in[15];
    const float* Wm2   = (const float*)d_in[16];
    const float* bm2   = (const float*)d_in[17];

    int N = in_sizes[0] / 2;
    int E = in_sizes[1] / 2;

    const int TB = 256;
    int gE    = (E + TB - 1) / TB;
    int gN    = (N + TB - 1) / TB;
    int gN8   = (N * 8 + TB - 1) / TB;
    int gAgg  = (N * 32 + 127) / 128;   // 128-thread blocks, warp per dst
    int gGemv = (N + 63) / 64;
    int nSB   = (N + 255) / 256;

    k_easum_hist_z0<<<512 + gN8, TB>>>(ei, (const float2*)ea,
                                       (const float2*)x, W0, b0, N, E);  // 0
    k_scan<<<nSB, 256>>>(N, E);                                          // 1
    k_scatter<<<gE + gN, TB>>>(ei, (const float2*)ea, N, E, gE);         // 2
    // layer 0
    k_agg<<<gAgg, 128>>>(We0, att0, bias0, (const int*)0, N);            // 3 (profiled)
    k_gemv<<<gGemv, 128>>>(W1, b1, N, 0);                                // 4
    // layer 1
    k_agg<<<gAgg, 128>>>(We1, att1, bias1, dest, N);                     // 5
    k_gemv<<<gGemv, 128>>>(Wm1, bm1, N, 1);                              // 6 (+gvec)
    // edge scoring head
    k_edge<<<gAgg, 128>>>(Wm1, Wm2, bm2, (float*)d_out, N);              // 7
}